// round 16
// baseline (speedup 1.0000x reference)
#include <cuda_runtime.h>
#include <cuda_fp16.h>
#include <cstdint>

// ============================================================================
// CAM: scores = b@c^T (NT), P = softmax(scores), out = P@a + a   per batch.
// B=16, C=1024, HW=1024.
// R16: same kernels as R15 (best-measured components), but launched as a
//      2-group batch pipeline on forked streams inside the captured graph:
//        s2:   split(g0), split(g1), transpose, softmax(g0)
//        main: GEMM1(g0), GEMM1(g1), softmax(g1), GEMM2(all)
//      DRAM-bound kernels hide under tensor-bound GEMMs (DRAM ~20% there).
// Base-ISA only (harness targets sm_103, no tcgen05).
// ============================================================================

#define BATCH 16
#define GRP 8                  // batches per pipeline group
#define NDIM 1024

__device__ __half g_b_hi[(size_t)BATCH * NDIM * NDIM];
__device__ __half g_b_lo[(size_t)BATCH * NDIM * NDIM];
__device__ __half g_c_hi[(size_t)BATCH * NDIM * NDIM];
__device__ __half g_c_lo[(size_t)BATCH * NDIM * NDIM];
__device__ __half g_at_hi[(size_t)BATCH * NDIM * NDIM];
__device__ __half g_p_hi[(size_t)BATCH * NDIM * NDIM];
__device__ float g_scores[(size_t)BATCH * NDIM * NDIM];

__device__ __forceinline__ uint32_t smem_u32(const void* p) {
    uint32_t a;
    asm("{ .reg .u64 t; cvta.to.shared.u64 t, %1; cvt.u32.u64 %0, t; }"
        : "=r"(a) : "l"(p));
    return a;
}

#define LDSM4(r0, r1, r2, r3, addr) \
    asm volatile("ldmatrix.sync.aligned.m8n8.x4.shared.b16 {%0,%1,%2,%3}, [%4];" \
                 : "=r"(r0), "=r"(r1), "=r"(r2), "=r"(r3) : "r"(addr))

#define MMA_F32(d, a, bb0, bb1) \
    asm volatile("mma.sync.aligned.m16n8k16.row.col.f32.f16.f16.f32 " \
                 "{%0,%1,%2,%3}, {%4,%5,%6,%7}, {%8,%9}, {%0,%1,%2,%3};" \
                 : "+f"((d)[0]), "+f"((d)[1]), "+f"((d)[2]), "+f"((d)[3]) \
                 : "r"((a)[0]), "r"((a)[1]), "r"((a)[2]), "r"((a)[3]), \
                   "r"(bb0), "r"(bb1))

#define MMA_F16(d, a, bb0, bb1) \
    asm volatile("mma.sync.aligned.m16n8k16.row.col.f16.f16.f16.f16 " \
                 "{%0,%1}, {%2,%3,%4,%5}, {%6,%7}, {%0,%1};" \
                 : "+r"((d)[0]), "+r"((d)[1]) \
                 : "r"((a)[0]), "r"((a)[1]), "r"((a)[2]), "r"((a)[3]), \
                   "r"(bb0), "r"(bb1))

__device__ __forceinline__ uint32_t swz(uint32_t base, int row, int ch) {
    return base + (uint32_t)(row * 128) + (uint32_t)(((ch ^ (row & 7)) & 7) * 16);
}

// ============================================================================
// 1) Split fp32 -> fp16 hi/lo for b and c (grid.y selects tensor)
// ============================================================================
__global__ __launch_bounds__(256)
void split_fp16_2(const float* __restrict__ b, const float* __restrict__ c,
                  __half* __restrict__ b_hi, __half* __restrict__ b_lo,
                  __half* __restrict__ c_hi, __half* __restrict__ c_lo) {
    const float* src = blockIdx.y ? c : b;
    __half* hi = blockIdx.y ? c_hi : b_hi;
    __half* lo = blockIdx.y ? c_lo : b_lo;
    size_t i = (size_t)blockIdx.x * blockDim.x + threadIdx.x;
    float4 v = ((const float4*)src)[i];
    __half hx = __float2half_rn(v.x), hy = __float2half_rn(v.y);
    __half hz = __float2half_rn(v.z), hw = __float2half_rn(v.w);
    float lx = v.x - __half2float(hx);
    float ly = v.y - __half2float(hy);
    float lz = v.z - __half2float(hz);
    float lw = v.w - __half2float(hw);
    ((__half2*)hi)[i * 2]     = __halves2half2(hx, hy);
    ((__half2*)hi)[i * 2 + 1] = __halves2half2(hz, hw);
    ((__half2*)lo)[i * 2]     = __halves2half2(__float2half_rn(lx), __float2half_rn(ly));
    ((__half2*)lo)[i * 2 + 1] = __halves2half2(__float2half_rn(lz), __float2half_rn(lw));
}

// ============================================================================
// 2) Transpose a[b][ch][hw] -> a_t[b][hw][ch], fp16 hi only
// ============================================================================
__global__ __launch_bounds__(256)
void transpose_half(const float* __restrict__ a, __half* __restrict__ at_hi) {
    __shared__ float tile[32][33];
    const size_t base = (size_t)blockIdx.z * NDIM * NDIM;
    const int tx = threadIdx.x, ty = threadIdx.y;
    const int x = blockIdx.x * 32 + tx;
    const int y0 = blockIdx.y * 32;
#pragma unroll
    for (int j = 0; j < 4; j++)
        tile[ty + j * 8][tx] = a[base + (size_t)(y0 + ty + j * 8) * NDIM + x];
    __syncthreads();
    const int x2 = blockIdx.y * 32 + tx;
    const int y20 = blockIdx.x * 32;
#pragma unroll
    for (int j = 0; j < 4; j++)
        at_hi[base + (size_t)(y20 + ty + j * 8) * NDIM + x2] =
            __float2half_rn(tile[tx][ty + j * 8]);
}

// ============================================================================
// 3) Row softmax (1024) -> fp16 P (hi only)
// ============================================================================
__global__ __launch_bounds__(256)
void cam_softmax(const float* __restrict__ S, __half* __restrict__ Phi) {
    __shared__ float wred[8];
    const size_t row = blockIdx.x;
    const float* p = S + row * NDIM;
    const int tid = threadIdx.x;
    const int lane = tid & 31;
    const int warp = tid >> 5;

    float4 v = *(const float4*)(p + tid * 4);
    float m = fmaxf(fmaxf(v.x, v.y), fmaxf(v.z, v.w));
#pragma unroll
    for (int off = 16; off > 0; off >>= 1)
        m = fmaxf(m, __shfl_xor_sync(0xFFFFFFFFu, m, off));
    if (lane == 0) wred[warp] = m;
    __syncthreads();
    m = wred[0];
#pragma unroll
    for (int w = 1; w < 8; w++) m = fmaxf(m, wred[w]);
    __syncthreads();

    v.x = __expf(v.x - m); v.y = __expf(v.y - m);
    v.z = __expf(v.z - m); v.w = __expf(v.w - m);
    float s = v.x + v.y + v.z + v.w;
#pragma unroll
    for (int off = 16; off > 0; off >>= 1)
        s += __shfl_xor_sync(0xFFFFFFFFu, s, off);
    if (lane == 0) wred[warp] = s;
    __syncthreads();
    s = 0.f;
#pragma unroll
    for (int w = 0; w < 8; w++) s += wred[w];
    const float inv = 1.0f / s;

    ((__half2*)(Phi + row * NDIM))[tid * 2] =
        __halves2half2(__float2half_rn(v.x * inv), __float2half_rn(v.y * inv));
    ((__half2*)(Phi + row * NDIM))[tid * 2 + 1] =
        __halves2half2(__float2half_rn(v.z * inv), __float2half_rn(v.w * inv));
}

// ============================================================================
// 4) GEMM1: 3-pass staged. CTA 128x128, KC=64, 3-stage cp.async,
//    8 warps 2x4, warp tile 64x32, 1 CTA/SM.
// ============================================================================
#define KC 64
#define NCHUNK (NDIM / KC)
#define TILE_B 16384
#define STAGE_B4 65536
#define SMEM_DYN4 (1024 + 3 * STAGE_B4)
#define STAGE_B2 32768
#define SMEM_DYN2 (1024 + 3 * STAGE_B2)

__global__ __launch_bounds__(256, 1)
void cam_gemm1(const __half* __restrict__ Ahi_g, const __half* __restrict__ Alo_g,
               const __half* __restrict__ Bhi_g, const __half* __restrict__ Blo_g,
               float* __restrict__ outp)
{
    extern __shared__ char smem_raw[];
    char* sbase_p = (char*)((((uintptr_t)smem_raw) + 1023) & ~(uintptr_t)1023);
    const uint32_t sbase = smem_u32(sbase_p);

    const int tid = threadIdx.x;
    const int l   = tid & 31;
    const int wid = tid >> 5;
    const int m0  = (wid >> 2) * 64;
    const int n0  = (wid & 3) * 32;

    const size_t bofs = (size_t)blockIdx.z * NDIM * NDIM;
    const int row0 = blockIdx.y * 128;
    const int col0 = blockIdx.x * 128;
    const __half* s0 = Ahi_g + bofs + (size_t)row0 * NDIM;
    const __half* s1 = Alo_g + bofs + (size_t)row0 * NDIM;
    const __half* s2 = Bhi_g + bofs + (size_t)col0 * NDIM;
    const __half* s3 = Blo_g + bofs + (size_t)col0 * NDIM;

    auto load_chunk = [&](int c, int buf) {
        const int k0 = c * KC;
        const uint32_t stage = sbase + (uint32_t)buf * STAGE_B4;
#pragma unroll
        for (int t = 0; t < 4; t++) {
            const __half* sp = (t == 0) ? s0 : (t == 1) ? s1 : (t == 2) ? s2 : s3;
#pragma unroll
            for (int jj = 0; jj < 4; jj++) {
                int slot = tid + 256 * jj;
                int row  = slot >> 3;
                int k16  = slot & 7;
                uint32_t dst = swz(stage + (uint32_t)t * TILE_B, row, k16);
                const __half* src = sp + (size_t)row * NDIM + k0 + k16 * 8;
                asm volatile("cp.async.cg.shared.global [%0], [%1], 16;"
                             :: "r"(dst), "l"(src));
            }
        }
        asm volatile("cp.async.commit_group;" ::: "memory");
    };

    float acc[4][4][4];
    uint32_t cacc[4][4][2];
#pragma unroll
    for (int i = 0; i < 4; i++)
#pragma unroll
        for (int j = 0; j < 4; j++) {
#pragma unroll
            for (int q = 0; q < 4; q++) acc[i][j][q] = 0.f;
            cacc[i][j][0] = 0u; cacc[i][j][1] = 0u;
        }

    const int a_row = l & 15;
    const int a_cs  = l >> 4;
    const int b_row = (l & 7) + ((l >> 4) << 3);
    const int b_cs  = (l >> 3) & 1;

    load_chunk(0, 0);
    load_chunk(1, 1);

    int buf = 0;
    for (int c = 0; c < NCHUNK; c++) {
        if (c == NCHUNK - 1) { asm volatile("cp.async.wait_group 0;" ::: "memory"); }
        else                 { asm volatile("cp.async.wait_group 1;" ::: "memory"); }
        __syncthreads();

        if (c + 2 < NCHUNK) {
            int nbuf = buf + 2; if (nbuf >= 3) nbuf -= 3;
            load_chunk(c + 2, nbuf);
        }

        const uint32_t st  = sbase + (uint32_t)buf * STAGE_B4;
        const uint32_t aHi = st;
        const uint32_t aLo = st + TILE_B;
        const uint32_t bHi = st + 2 * TILE_B;
        const uint32_t bLo = st + 3 * TILE_B;

#pragma unroll
        for (int k16 = 0; k16 < 4; k16++) {
            const int chA = 2 * k16 + a_cs;
            const int chB = 2 * k16 + b_cs;

            uint32_t ah[4][4], al[4][4];
            uint32_t bh[4][2], bl[4][2];
#pragma unroll
            for (int i = 0; i < 4; i++) {
                const int r = m0 + i * 16 + a_row;
                LDSM4(ah[i][0], ah[i][1], ah[i][2], ah[i][3], swz(aHi, r, chA));
                LDSM4(al[i][0], al[i][1], al[i][2], al[i][3], swz(aLo, r, chA));
            }
#pragma unroll
            for (int j = 0; j < 2; j++) {
                const int r = n0 + j * 16 + b_row;
                LDSM4(bh[2*j][0], bh[2*j][1], bh[2*j+1][0], bh[2*j+1][1], swz(bHi, r, chB));
                LDSM4(bl[2*j][0], bl[2*j][1], bl[2*j+1][0], bl[2*j+1][1], swz(bLo, r, chB));
            }
#pragma unroll
            for (int i = 0; i < 4; i++)
#pragma unroll
                for (int j = 0; j < 4; j++) {
                    MMA_F32(acc[i][j], ah[i], bh[j][0], bh[j][1]);
                    MMA_F16(cacc[i][j], ah[i], bl[j][0], bl[j][1]);
                    MMA_F16(cacc[i][j], al[i], bh[j][0], bh[j][1]);
                }
        }
        buf++; if (buf >= 3) buf = 0;
    }

    float* outb = outp + bofs;
    const int er = l >> 2;
    const int ec = (l & 3) * 2;
#pragma unroll
    for (int i = 0; i < 4; i++) {
        const int grow = row0 + m0 + i * 16 + er;
#pragma unroll
        for (int j = 0; j < 4; j++) {
            const int gcol = col0 + n0 + j * 8 + ec;
            size_t o0 = (size_t)grow * NDIM + gcol;
            size_t o1 = (size_t)(grow + 8) * NDIM + gcol;
            __half2 c01 = *reinterpret_cast<__half2*>(&cacc[i][j][0]);
            __half2 c23 = *reinterpret_cast<__half2*>(&cacc[i][j][1]);
            *(float2*)(outb + o0) = make_float2(acc[i][j][0] + __low2float(c01),
                                                acc[i][j][1] + __high2float(c01));
            *(float2*)(outb + o1) = make_float2(acc[i][j][2] + __low2float(c23),
                                                acc[i][j][3] + __high2float(c23));
        }
    }
}

// ============================================================================
// 5) GEMM2: single-pass, 128 threads, 2x2 warps, 64x64 warp tile.
// ============================================================================
__global__ __launch_bounds__(128, 2)
void cam_gemm2(const __half* __restrict__ P_g, const __half* __restrict__ Bhi_g,
               const float* __restrict__ resid, float* __restrict__ outp)
{
    extern __shared__ char smem_raw[];
    char* sbase_p = (char*)((((uintptr_t)smem_raw) + 1023) & ~(uintptr_t)1023);
    const uint32_t sbase = smem_u32(sbase_p);

    const int tid = threadIdx.x;
    const int l   = tid & 31;
    const int wid = tid >> 5;
    const int m0  = (wid >> 1) * 64;
    const int n0  = (wid & 1) * 64;

    const size_t bofs = (size_t)blockIdx.z * NDIM * NDIM;
    const int row0 = blockIdx.y * 128;
    const int col0 = blockIdx.x * 128;
    const __half* s0 = P_g   + bofs + (size_t)row0 * NDIM;
    const __half* s2 = Bhi_g + bofs + (size_t)col0 * NDIM;

    auto load_chunk = [&](int c, int buf) {
        const int k0 = c * KC;
        const uint32_t stage = sbase + (uint32_t)buf * STAGE_B2;
#pragma unroll
        for (int jj = 0; jj < 16; jj++) {
            int slot = tid + 128 * jj;
            int t    = slot >> 10;
            int row  = (slot >> 3) & 127;
            int k16  = slot & 7;
            uint32_t dst = swz(stage + (uint32_t)t * TILE_B, row, k16);
            const __half* src = (t ? s2 : s0) + (size_t)row * NDIM + k0 + k16 * 8;
            asm volatile("cp.async.cg.shared.global [%0], [%1], 16;"
                         :: "r"(dst), "l"(src));
        }
        asm volatile("cp.async.commit_group;" ::: "memory");
    };

    float acc[4][8][4];
#pragma unroll
    for (int i = 0; i < 4; i++)
#pragma unroll
        for (int j = 0; j < 8; j++)
#pragma unroll
            for (int q = 0; q < 4; q++) acc[i][j][q] = 0.f;

    const int a_row = l & 15;
    const int a_cs  = l >> 4;
    const int b_row = (l & 7) + ((l >> 4) << 3);
    const int b_cs  = (l >> 3) & 1;

    load_chunk(0, 0);
    load_chunk(1, 1);

    int buf = 0;
    for (int c = 0; c < NCHUNK; c++) {
        if (c == NCHUNK - 1) { asm volatile("cp.async.wait_group 0;" ::: "memory"); }
        else                 { asm volatile("cp.async.wait_group 1;" ::: "memory"); }
        __syncthreads();

        if (c + 2 < NCHUNK) {
            int nbuf = buf + 2; if (nbuf >= 3) nbuf -= 3;
            load_chunk(c + 2, nbuf);
        }

        const uint32_t st  = sbase + (uint32_t)buf * STAGE_B2;
        const uint32_t aP  = st;
        const uint32_t bHi = st + TILE_B;

#pragma unroll
        for (int k16 = 0; k16 < 4; k16++) {
            const int chA = 2 * k16 + a_cs;
            const int chB = 2 * k16 + b_cs;

            uint32_t af[4][4];
            uint32_t bh[8][2];
#pragma unroll
            for (int i = 0; i < 4; i++) {
                const int r = m0 + i * 16 + a_row;
                LDSM4(af[i][0], af[i][1], af[i][2], af[i][3], swz(aP, r, chA));
            }
#pragma unroll
            for (int j = 0; j < 4; j++) {
                const int r = n0 + j * 16 + b_row;
                LDSM4(bh[2*j][0], bh[2*j][1], bh[2*j+1][0], bh[2*j+1][1], swz(bHi, r, chB));
            }
#pragma unroll
            for (int i = 0; i < 4; i++)
#pragma unroll
                for (int j = 0; j < 8; j++)
                    MMA_F32(acc[i][j], af[i], bh[j][0], bh[j][1]);
        }
        buf++; if (buf >= 3) buf = 0;
    }

    float* outb = outp + bofs;
    const float* resb = resid + bofs;
    const int er = l >> 2;
    const int ec = (l & 3) * 2;
#pragma unroll
    for (int i = 0; i < 4; i++) {
        const int grow = row0 + m0 + i * 16 + er;
#pragma unroll
        for (int j = 0; j < 8; j++) {
            const int gcol = col0 + n0 + j * 8 + ec;
            size_t o0 = (size_t)grow * NDIM + gcol;
            size_t o1 = (size_t)(grow + 8) * NDIM + gcol;
            float2 r0 = *(const float2*)(resb + o0);
            float2 r1 = *(const float2*)(resb + o1);
            *(float2*)(outb + o0) = make_float2(acc[i][j][0] + r0.x,
                                                acc[i][j][1] + r0.y);
            *(float2*)(outb + o1) = make_float2(acc[i][j][2] + r1.x,
                                                acc[i][j][3] + r1.y);
        }
    }
}

// ============================================================================
// Launch: 2-group batch pipeline via forked streams (graph-capturable).
// ============================================================================
extern "C" void kernel_launch(void* const* d_in, const int* in_sizes, int n_in,
                              void* d_out, int out_size) {
    const float* a = (const float*)d_in[0];
    const float* b = (const float*)d_in[1];
    const float* c = (const float*)d_in[2];
    float* out = (float*)d_out;

    __half *b_hi, *b_lo, *c_hi, *c_lo, *at_hi, *p_hi;
    float* scores;
    cudaGetSymbolAddress((void**)&b_hi, g_b_hi);
    cudaGetSymbolAddress((void**)&b_lo, g_b_lo);
    cudaGetSymbolAddress((void**)&c_hi, g_c_hi);
    cudaGetSymbolAddress((void**)&c_lo, g_c_lo);
    cudaGetSymbolAddress((void**)&at_hi, g_at_hi);
    cudaGetSymbolAddress((void**)&p_hi, g_p_hi);
    cudaGetSymbolAddress((void**)&scores, g_scores);

    cudaFuncSetAttribute((const void*)cam_gemm1,
                         cudaFuncAttributeMaxDynamicSharedMemorySize, SMEM_DYN4);
    cudaFuncSetAttribute((const void*)cam_gemm2,
                         cudaFuncAttributeMaxDynamicSharedMemorySize, SMEM_DYN2);

    const size_t GOFS = (size_t)GRP * NDIM * NDIM;       // elements per group
    const int gn4blk = (int)(GOFS / 4 / 256);            // split grid.x per group

    // streams/events created fresh each call (not captured ops; leaked —
    // host-side only, kernel_launch is invoked a handful of times).
    cudaStream_t s2;
    cudaStreamCreateWithFlags(&s2, cudaStreamNonBlocking);
    cudaEvent_t evRoot, ev0, ev1, evT, evG10, evSm0;
    cudaEventCreateWithFlags(&evRoot, cudaEventDisableTiming);
    cudaEventCreateWithFlags(&ev0,    cudaEventDisableTiming);
    cudaEventCreateWithFlags(&ev1,    cudaEventDisableTiming);
    cudaEventCreateWithFlags(&evT,    cudaEventDisableTiming);
    cudaEventCreateWithFlags(&evG10,  cudaEventDisableTiming);
    cudaEventCreateWithFlags(&evSm0,  cudaEventDisableTiming);

    // fork s2 from the (possibly capturing) default stream
    cudaEventRecord(evRoot, 0);
    cudaStreamWaitEvent(s2, evRoot, 0);

    // --- s2: producer chain ---
    split_fp16_2<<<dim3(gn4blk, 2), 256, 0, s2>>>(b, c, b_hi, b_lo, c_hi, c_lo);
    cudaEventRecord(ev0, s2);
    split_fp16_2<<<dim3(gn4blk, 2), 256, 0, s2>>>(b + GOFS, c + GOFS,
                                                  b_hi + GOFS, b_lo + GOFS,
                                                  c_hi + GOFS, c_lo + GOFS);
    cudaEventRecord(ev1, s2);
    transpose_half<<<dim3(32, 32, BATCH), dim3(32, 8), 0, s2>>>(a, at_hi);
    cudaEventRecord(evT, s2);

    // --- main stream: GEMM1 group 0 ---
    cudaStreamWaitEvent(0, ev0, 0);
    dim3 ggrid(8, 8, GRP);
    cam_gemm1<<<ggrid, 256, SMEM_DYN4>>>(b_hi, b_lo, c_hi, c_lo, scores);
    cudaEventRecord(evG10, 0);

    // --- s2: softmax group 0 overlaps GEMM1 group 1 ---
    cudaStreamWaitEvent(s2, evG10, 0);
    cam_softmax<<<GRP * NDIM, 256, 0, s2>>>(scores, p_hi);
    cudaEventRecord(evSm0, s2);

    // --- main stream: GEMM1 group 1, softmax group 1 ---
    cudaStreamWaitEvent(0, ev1, 0);
    cam_gemm1<<<ggrid, 256, SMEM_DYN4>>>(b_hi + GOFS, b_lo + GOFS,
                                         c_hi + GOFS, c_lo + GOFS,
                                         scores + GOFS);
    cam_softmax<<<GRP * NDIM, 256>>>(scores + GOFS, p_hi + GOFS);

    // --- join: GEMM2 over all batches ---
    cudaStreamWaitEvent(0, evSm0, 0);
    cudaStreamWaitEvent(0, evT, 0);
    cam_gemm2<<<dim3(8, 8, BATCH), 128, SMEM_DYN2>>>(p_hi, at_hi, a, out);
}

// round 17
// speedup vs baseline: 1.0302x; 1.0302x over previous
#include <cuda_runtime.h>
#include <cuda_fp16.h>
#include <cstdint>

// ============================================================================
// CAM: scores = b@c^T (NT), P = softmax(scores), out = P@a + a   per batch.
// B=16, C=1024, HW=1024.
//   split:  fp32 -> fp16 hi/lo for b and c. R17: 16 floats/thread, MLP=4,
//           16B vector stores (DRAM-roofline push).
//   GEMM1 (3-pass, staged): KC=64, 3-stage cp.async, 64x32 warp tile.
//   GEMM2 (1-pass): Phi*ahi -> f32 acc; 2x2 warps, 64x64 warp tile, 128 thr.
// Base-ISA only (harness targets sm_103, no tcgen05). Serial launches.
// ============================================================================

#define BATCH 16
#define NDIM 1024

__device__ __half g_b_hi[(size_t)BATCH * NDIM * NDIM];
__device__ __half g_b_lo[(size_t)BATCH * NDIM * NDIM];
__device__ __half g_c_hi[(size_t)BATCH * NDIM * NDIM];
__device__ __half g_c_lo[(size_t)BATCH * NDIM * NDIM];
__device__ __half g_at_hi[(size_t)BATCH * NDIM * NDIM];
__device__ __half g_p_hi[(size_t)BATCH * NDIM * NDIM];
__device__ float g_scores[(size_t)BATCH * NDIM * NDIM];

__device__ __forceinline__ uint32_t smem_u32(const void* p) {
    uint32_t a;
    asm("{ .reg .u64 t; cvta.to.shared.u64 t, %1; cvt.u32.u64 %0, t; }"
        : "=r"(a) : "l"(p));
    return a;
}

#define LDSM4(r0, r1, r2, r3, addr) \
    asm volatile("ldmatrix.sync.aligned.m8n8.x4.shared.b16 {%0,%1,%2,%3}, [%4];" \
                 : "=r"(r0), "=r"(r1), "=r"(r2), "=r"(r3) : "r"(addr))

#define MMA_F32(d, a, bb0, bb1) \
    asm volatile("mma.sync.aligned.m16n8k16.row.col.f32.f16.f16.f32 " \
                 "{%0,%1,%2,%3}, {%4,%5,%6,%7}, {%8,%9}, {%0,%1,%2,%3};" \
                 : "+f"((d)[0]), "+f"((d)[1]), "+f"((d)[2]), "+f"((d)[3]) \
                 : "r"((a)[0]), "r"((a)[1]), "r"((a)[2]), "r"((a)[3]), \
                   "r"(bb0), "r"(bb1))

#define MMA_F16(d, a, bb0, bb1) \
    asm volatile("mma.sync.aligned.m16n8k16.row.col.f16.f16.f16.f16 " \
                 "{%0,%1}, {%2,%3,%4,%5}, {%6,%7}, {%0,%1};" \
                 : "+r"((d)[0]), "+r"((d)[1]) \
                 : "r"((a)[0]), "r"((a)[1]), "r"((a)[2]), "r"((a)[3]), \
                   "r"(bb0), "r"(bb1))

__device__ __forceinline__ uint32_t swz(uint32_t base, int row, int ch) {
    return base + (uint32_t)(row * 128) + (uint32_t)(((ch ^ (row & 7)) & 7) * 16);
}

// ============================================================================
// 1) Split fp32 -> fp16 hi/lo, 16 floats/thread, MLP=4, 16B stores.
//    grid: (total_float4 / 1024, 2); each block covers 1024 float4s.
// ============================================================================
__global__ __launch_bounds__(256)
void split_fp16_2(const float* __restrict__ b, const float* __restrict__ c,
                  __half* __restrict__ b_hi, __half* __restrict__ b_lo,
                  __half* __restrict__ c_hi, __half* __restrict__ c_lo) {
    const float4* src = (const float4*)(blockIdx.y ? c : b);
    uint4* hi = (uint4*)(blockIdx.y ? c_hi : b_hi);
    uint4* lo = (uint4*)(blockIdx.y ? c_lo : b_lo);

    const size_t p0 = (size_t)blockIdx.x * 1024 + (size_t)threadIdx.x * 2;

    // 4 independent loads in flight (MLP=4)
    float4 v0 = src[p0];
    float4 v1 = src[p0 + 1];
    float4 v2 = src[p0 + 512];
    float4 v3 = src[p0 + 513];

    auto cvt16 = [](float4 a0, float4 a1, uint4& h, uint4& l) {
        __half2 h0 = __floats2half2_rn(a0.x, a0.y);
        __half2 h1 = __floats2half2_rn(a0.z, a0.w);
        __half2 h2 = __floats2half2_rn(a1.x, a1.y);
        __half2 h3 = __floats2half2_rn(a1.z, a1.w);
        __half2 l0 = __floats2half2_rn(a0.x - __half2float(__low2half(h0)),
                                       a0.y - __half2float(__high2half(h0)));
        __half2 l1 = __floats2half2_rn(a0.z - __half2float(__low2half(h1)),
                                       a0.w - __half2float(__high2half(h1)));
        __half2 l2 = __floats2half2_rn(a1.x - __half2float(__low2half(h2)),
                                       a1.y - __half2float(__high2half(h2)));
        __half2 l3 = __floats2half2_rn(a1.z - __half2float(__low2half(h3)),
                                       a1.w - __half2float(__high2half(h3)));
        h = make_uint4(*(uint32_t*)&h0, *(uint32_t*)&h1,
                       *(uint32_t*)&h2, *(uint32_t*)&h3);
        l = make_uint4(*(uint32_t*)&l0, *(uint32_t*)&l1,
                       *(uint32_t*)&l2, *(uint32_t*)&l3);
    };

    uint4 ha, la, hb2, lb2;
    cvt16(v0, v1, ha, la);
    cvt16(v2, v3, hb2, lb2);
    hi[p0 >> 1]         = ha;
    lo[p0 >> 1]         = la;
    hi[(p0 + 512) >> 1] = hb2;
    lo[(p0 + 512) >> 1] = lb2;
}

// ============================================================================
// 2) Transpose a[b][ch][hw] -> a_t[b][hw][ch], fp16 hi only
// ============================================================================
__global__ __launch_bounds__(256)
void transpose_half(const float* __restrict__ a, __half* __restrict__ at_hi) {
    __shared__ float tile[32][33];
    const size_t base = (size_t)blockIdx.z * NDIM * NDIM;
    const int tx = threadIdx.x, ty = threadIdx.y;
    const int x = blockIdx.x * 32 + tx;
    const int y0 = blockIdx.y * 32;
#pragma unroll
    for (int j = 0; j < 4; j++)
        tile[ty + j * 8][tx] = a[base + (size_t)(y0 + ty + j * 8) * NDIM + x];
    __syncthreads();
    const int x2 = blockIdx.y * 32 + tx;
    const int y20 = blockIdx.x * 32;
#pragma unroll
    for (int j = 0; j < 4; j++)
        at_hi[base + (size_t)(y20 + ty + j * 8) * NDIM + x2] =
            __float2half_rn(tile[tx][ty + j * 8]);
}

// ============================================================================
// 3) Row softmax (1024) -> fp16 P (hi only)
// ============================================================================
__global__ __launch_bounds__(256)
void cam_softmax(const float* __restrict__ S, __half* __restrict__ Phi) {
    __shared__ float wred[8];
    const size_t row = blockIdx.x;
    const float* p = S + row * NDIM;
    const int tid = threadIdx.x;
    const int lane = tid & 31;
    const int warp = tid >> 5;

    float4 v = *(const float4*)(p + tid * 4);
    float m = fmaxf(fmaxf(v.x, v.y), fmaxf(v.z, v.w));
#pragma unroll
    for (int off = 16; off > 0; off >>= 1)
        m = fmaxf(m, __shfl_xor_sync(0xFFFFFFFFu, m, off));
    if (lane == 0) wred[warp] = m;
    __syncthreads();
    m = wred[0];
#pragma unroll
    for (int w = 1; w < 8; w++) m = fmaxf(m, wred[w]);
    __syncthreads();

    v.x = __expf(v.x - m); v.y = __expf(v.y - m);
    v.z = __expf(v.z - m); v.w = __expf(v.w - m);
    float s = v.x + v.y + v.z + v.w;
#pragma unroll
    for (int off = 16; off > 0; off >>= 1)
        s += __shfl_xor_sync(0xFFFFFFFFu, s, off);
    if (lane == 0) wred[warp] = s;
    __syncthreads();
    s = 0.f;
#pragma unroll
    for (int w = 0; w < 8; w++) s += wred[w];
    const float inv = 1.0f / s;

    ((__half2*)(Phi + row * NDIM))[tid * 2] =
        __halves2half2(__float2half_rn(v.x * inv), __float2half_rn(v.y * inv));
    ((__half2*)(Phi + row * NDIM))[tid * 2 + 1] =
        __halves2half2(__float2half_rn(v.z * inv), __float2half_rn(v.w * inv));
}

// ============================================================================
// 4) GEMM1: 3-pass staged. CTA 128x128, KC=64, 3-stage cp.async,
//    8 warps 2x4, warp tile 64x32, 1 CTA/SM.
// ============================================================================
#define KC 64
#define NCHUNK (NDIM / KC)
#define TILE_B 16384
#define STAGE_B4 65536
#define SMEM_DYN4 (1024 + 3 * STAGE_B4)
#define STAGE_B2 32768
#define SMEM_DYN2 (1024 + 3 * STAGE_B2)

__global__ __launch_bounds__(256, 1)
void cam_gemm1(const __half* __restrict__ Ahi_g, const __half* __restrict__ Alo_g,
               const __half* __restrict__ Bhi_g, const __half* __restrict__ Blo_g,
               float* __restrict__ outp)
{
    extern __shared__ char smem_raw[];
    char* sbase_p = (char*)((((uintptr_t)smem_raw) + 1023) & ~(uintptr_t)1023);
    const uint32_t sbase = smem_u32(sbase_p);

    const int tid = threadIdx.x;
    const int l   = tid & 31;
    const int wid = tid >> 5;
    const int m0  = (wid >> 2) * 64;
    const int n0  = (wid & 3) * 32;

    const size_t bofs = (size_t)blockIdx.z * NDIM * NDIM;
    const int row0 = blockIdx.y * 128;
    const int col0 = blockIdx.x * 128;
    const __half* s0 = Ahi_g + bofs + (size_t)row0 * NDIM;
    const __half* s1 = Alo_g + bofs + (size_t)row0 * NDIM;
    const __half* s2 = Bhi_g + bofs + (size_t)col0 * NDIM;
    const __half* s3 = Blo_g + bofs + (size_t)col0 * NDIM;

    auto load_chunk = [&](int c, int buf) {
        const int k0 = c * KC;
        const uint32_t stage = sbase + (uint32_t)buf * STAGE_B4;
#pragma unroll
        for (int t = 0; t < 4; t++) {
            const __half* sp = (t == 0) ? s0 : (t == 1) ? s1 : (t == 2) ? s2 : s3;
#pragma unroll
            for (int jj = 0; jj < 4; jj++) {
                int slot = tid + 256 * jj;
                int row  = slot >> 3;
                int k16  = slot & 7;
                uint32_t dst = swz(stage + (uint32_t)t * TILE_B, row, k16);
                const __half* src = sp + (size_t)row * NDIM + k0 + k16 * 8;
                asm volatile("cp.async.cg.shared.global [%0], [%1], 16;"
                             :: "r"(dst), "l"(src));
            }
        }
        asm volatile("cp.async.commit_group;" ::: "memory");
    };

    float acc[4][4][4];
    uint32_t cacc[4][4][2];
#pragma unroll
    for (int i = 0; i < 4; i++)
#pragma unroll
        for (int j = 0; j < 4; j++) {
#pragma unroll
            for (int q = 0; q < 4; q++) acc[i][j][q] = 0.f;
            cacc[i][j][0] = 0u; cacc[i][j][1] = 0u;
        }

    const int a_row = l & 15;
    const int a_cs  = l >> 4;
    const int b_row = (l & 7) + ((l >> 4) << 3);
    const int b_cs  = (l >> 3) & 1;

    load_chunk(0, 0);
    load_chunk(1, 1);

    int buf = 0;
    for (int c = 0; c < NCHUNK; c++) {
        if (c == NCHUNK - 1) { asm volatile("cp.async.wait_group 0;" ::: "memory"); }
        else                 { asm volatile("cp.async.wait_group 1;" ::: "memory"); }
        __syncthreads();

        if (c + 2 < NCHUNK) {
            int nbuf = buf + 2; if (nbuf >= 3) nbuf -= 3;
            load_chunk(c + 2, nbuf);
        }

        const uint32_t st  = sbase + (uint32_t)buf * STAGE_B4;
        const uint32_t aHi = st;
        const uint32_t aLo = st + TILE_B;
        const uint32_t bHi = st + 2 * TILE_B;
        const uint32_t bLo = st + 3 * TILE_B;

#pragma unroll
        for (int k16 = 0; k16 < 4; k16++) {
            const int chA = 2 * k16 + a_cs;
            const int chB = 2 * k16 + b_cs;

            uint32_t ah[4][4], al[4][4];
            uint32_t bh[4][2], bl[4][2];
#pragma unroll
            for (int i = 0; i < 4; i++) {
                const int r = m0 + i * 16 + a_row;
                LDSM4(ah[i][0], ah[i][1], ah[i][2], ah[i][3], swz(aHi, r, chA));
                LDSM4(al[i][0], al[i][1], al[i][2], al[i][3], swz(aLo, r, chA));
            }
#pragma unroll
            for (int j = 0; j < 2; j++) {
                const int r = n0 + j * 16 + b_row;
                LDSM4(bh[2*j][0], bh[2*j][1], bh[2*j+1][0], bh[2*j+1][1], swz(bHi, r, chB));
                LDSM4(bl[2*j][0], bl[2*j][1], bl[2*j+1][0], bl[2*j+1][1], swz(bLo, r, chB));
            }
#pragma unroll
            for (int i = 0; i < 4; i++)
#pragma unroll
                for (int j = 0; j < 4; j++) {
                    MMA_F32(acc[i][j], ah[i], bh[j][0], bh[j][1]);
                    MMA_F16(cacc[i][j], ah[i], bl[j][0], bl[j][1]);
                    MMA_F16(cacc[i][j], al[i], bh[j][0], bh[j][1]);
                }
        }
        buf++; if (buf >= 3) buf = 0;
    }

    float* outb = outp + bofs;
    const int er = l >> 2;
    const int ec = (l & 3) * 2;
#pragma unroll
    for (int i = 0; i < 4; i++) {
        const int grow = row0 + m0 + i * 16 + er;
#pragma unroll
        for (int j = 0; j < 4; j++) {
            const int gcol = col0 + n0 + j * 8 + ec;
            size_t o0 = (size_t)grow * NDIM + gcol;
            size_t o1 = (size_t)(grow + 8) * NDIM + gcol;
            __half2 c01 = *reinterpret_cast<__half2*>(&cacc[i][j][0]);
            __half2 c23 = *reinterpret_cast<__half2*>(&cacc[i][j][1]);
            *(float2*)(outb + o0) = make_float2(acc[i][j][0] + __low2float(c01),
                                                acc[i][j][1] + __high2float(c01));
            *(float2*)(outb + o1) = make_float2(acc[i][j][2] + __low2float(c23),
                                                acc[i][j][3] + __high2float(c23));
        }
    }
}

// ============================================================================
// 5) GEMM2: single-pass, 128 threads, 2x2 warps, 64x64 warp tile.
// ============================================================================
__global__ __launch_bounds__(128, 2)
void cam_gemm2(const __half* __restrict__ P_g, const __half* __restrict__ Bhi_g,
               const float* __restrict__ resid, float* __restrict__ outp)
{
    extern __shared__ char smem_raw[];
    char* sbase_p = (char*)((((uintptr_t)smem_raw) + 1023) & ~(uintptr_t)1023);
    const uint32_t sbase = smem_u32(sbase_p);

    const int tid = threadIdx.x;
    const int l   = tid & 31;
    const int wid = tid >> 5;
    const int m0  = (wid >> 1) * 64;
    const int n0  = (wid & 1) * 64;

    const size_t bofs = (size_t)blockIdx.z * NDIM * NDIM;
    const int row0 = blockIdx.y * 128;
    const int col0 = blockIdx.x * 128;
    const __half* s0 = P_g   + bofs + (size_t)row0 * NDIM;
    const __half* s2 = Bhi_g + bofs + (size_t)col0 * NDIM;

    auto load_chunk = [&](int c, int buf) {
        const int k0 = c * KC;
        const uint32_t stage = sbase + (uint32_t)buf * STAGE_B2;
#pragma unroll
        for (int jj = 0; jj < 16; jj++) {
            int slot = tid + 128 * jj;
            int t    = slot >> 10;
            int row  = (slot >> 3) & 127;
            int k16  = slot & 7;
            uint32_t dst = swz(stage + (uint32_t)t * TILE_B, row, k16);
            const __half* src = (t ? s2 : s0) + (size_t)row * NDIM + k0 + k16 * 8;
            asm volatile("cp.async.cg.shared.global [%0], [%1], 16;"
                         :: "r"(dst), "l"(src));
        }
        asm volatile("cp.async.commit_group;" ::: "memory");
    };

    float acc[4][8][4];
#pragma unroll
    for (int i = 0; i < 4; i++)
#pragma unroll
        for (int j = 0; j < 8; j++)
#pragma unroll
            for (int q = 0; q < 4; q++) acc[i][j][q] = 0.f;

    const int a_row = l & 15;
    const int a_cs  = l >> 4;
    const int b_row = (l & 7) + ((l >> 4) << 3);
    const int b_cs  = (l >> 3) & 1;

    load_chunk(0, 0);
    load_chunk(1, 1);

    int buf = 0;
    for (int c = 0; c < NCHUNK; c++) {
        if (c == NCHUNK - 1) { asm volatile("cp.async.wait_group 0;" ::: "memory"); }
        else                 { asm volatile("cp.async.wait_group 1;" ::: "memory"); }
        __syncthreads();

        if (c + 2 < NCHUNK) {
            int nbuf = buf + 2; if (nbuf >= 3) nbuf -= 3;
            load_chunk(c + 2, nbuf);
        }

        const uint32_t st  = sbase + (uint32_t)buf * STAGE_B2;
        const uint32_t aP  = st;
        const uint32_t bHi = st + TILE_B;

#pragma unroll
        for (int k16 = 0; k16 < 4; k16++) {
            const int chA = 2 * k16 + a_cs;
            const int chB = 2 * k16 + b_cs;

            uint32_t af[4][4];
            uint32_t bh[8][2];
#pragma unroll
            for (int i = 0; i < 4; i++) {
                const int r = m0 + i * 16 + a_row;
                LDSM4(af[i][0], af[i][1], af[i][2], af[i][3], swz(aP, r, chA));
            }
#pragma unroll
            for (int j = 0; j < 4; j++) {
                const int r = n0 + j * 16 + b_row;
                LDSM4(bh[2*j][0], bh[2*j][1], bh[2*j+1][0], bh[2*j+1][1], swz(bHi, r, chB));
            }
#pragma unroll
            for (int i = 0; i < 4; i++)
#pragma unroll
                for (int j = 0; j < 8; j++)
                    MMA_F32(acc[i][j], af[i], bh[j][0], bh[j][1]);
        }
        buf++; if (buf >= 3) buf = 0;
    }

    float* outb = outp + bofs;
    const float* resb = resid + bofs;
    const int er = l >> 2;
    const int ec = (l & 3) * 2;
#pragma unroll
    for (int i = 0; i < 4; i++) {
        const int grow = row0 + m0 + i * 16 + er;
#pragma unroll
        for (int j = 0; j < 8; j++) {
            const int gcol = col0 + n0 + j * 8 + ec;
            size_t o0 = (size_t)grow * NDIM + gcol;
            size_t o1 = (size_t)(grow + 8) * NDIM + gcol;
            float2 r0 = *(const float2*)(resb + o0);
            float2 r1 = *(const float2*)(resb + o1);
            *(float2*)(outb + o0) = make_float2(acc[i][j][0] + r0.x,
                                                acc[i][j][1] + r0.y);
            *(float2*)(outb + o1) = make_float2(acc[i][j][2] + r1.x,
                                                acc[i][j][3] + r1.y);
        }
    }
}

// ============================================================================
extern "C" void kernel_launch(void* const* d_in, const int* in_sizes, int n_in,
                              void* d_out, int out_size) {
    const float* a = (const float*)d_in[0];
    const float* b = (const float*)d_in[1];
    const float* c = (const float*)d_in[2];
    float* out = (float*)d_out;

    __half *b_hi, *b_lo, *c_hi, *c_lo, *at_hi, *p_hi;
    float* scores;
    cudaGetSymbolAddress((void**)&b_hi, g_b_hi);
    cudaGetSymbolAddress((void**)&b_lo, g_b_lo);
    cudaGetSymbolAddress((void**)&c_hi, g_c_hi);
    cudaGetSymbolAddress((void**)&c_lo, g_c_lo);
    cudaGetSymbolAddress((void**)&at_hi, g_at_hi);
    cudaGetSymbolAddress((void**)&p_hi, g_p_hi);
    cudaGetSymbolAddress((void**)&scores, g_scores);

    cudaFuncSetAttribute((const void*)cam_gemm1,
                         cudaFuncAttributeMaxDynamicSharedMemorySize, SMEM_DYN4);
    cudaFuncSetAttribute((const void*)cam_gemm2,
                         cudaFuncAttributeMaxDynamicSharedMemorySize, SMEM_DYN2);

    // split: total float4 per tensor = 16M/4 = 4M; 1024 float4/block -> 4096
    const int nblk = (BATCH * NDIM * NDIM) / 4 / 1024;
    split_fp16_2<<<dim3(nblk, 2), 256>>>(b, c, b_hi, b_lo, c_hi, c_lo);
    transpose_half<<<dim3(32, 32, BATCH), dim3(32, 8)>>>(a, at_hi);

    dim3 grid(8, 8, BATCH);
    cam_gemm1<<<grid, 256, SMEM_DYN4>>>(b_hi, b_lo, c_hi, c_lo, scores);
    cam_softmax<<<BATCH * NDIM, 256>>>(scores, p_hi);
    cam_gemm2<<<grid, 128, SMEM_DYN2>>>(p_hi, at_hi, a, out);
}